// round 11
// baseline (speedup 1.0000x reference)
#include <cuda_runtime.h>
#include <cstdint>

// MultiLIF: I[B=32, L=2048, K=512] -> (spikes[B,L,K], spike_series[B,L,K])
// d_out: spikes (B*L*K floats) then spike_series.
//
// R11: two-phase decomposition.
//  Phase 1 (latency-bound, 512 warps): LIF recurrence only. Emits one 32-bit
//    spike bitmask per warp-step (4 MB) + per-neuron n checkpoints every 256
//    steps (512 KB). No bulk output stores -> LSU pressure ~1/3 of R7.
//  Phase 2 (bandwidth-bound, 4096 warps): time is parallel given the masks.
//    Each warp expands one (neuron-warp, 256-step chunk): s = mask bit
//    (exact {0,1}), n = checkpoint + exact integer float accumulation
//    (all integers < 2^24 -> bit-identical to reference), streams all
//    268 MB of output at full DRAM bandwidth.

static constexpr int B_ = 32;
static constexpr int L_ = 2048;
static constexpr int K_ = 512;
static constexpr int NWARP = (B_ * K_) / 32;     // 512 neuron-warps
static constexpr int UNROLL = 8;                 // phase-1 steps per batch
static constexpr int NBUF = 8;                   // phase-1 input ring depth
static constexpr int NBATCH = L_ / UNROLL;       // 256
static constexpr int STRIDE = UNROLL * K_;
static constexpr int CHUNK = 256;                // phase-2 steps per warp
static constexpr int NCHUNK = L_ / CHUNK;        // 8

__device__ uint32_t g_masks[NWARP][L_];          // 4 MB  [neuron-warp][t]
__device__ float    g_nckpt[NCHUNK][B_ * K_];    // 512 KB [chunk][neuron]

__device__ __forceinline__ float div_const_rn(float x, float b, float y)
{
    // Markstein: correctly-rounded RN(x/b), y = RN(1/b). Branch-free;
    // == __fdiv_rn for all values reachable here.
    float q0 = __fmul_rn(x, y);
    float r  = __fmaf_rn(-b, q0, x);
    return __fmaf_rn(r, y, q0);
}

// ---------------------------------------------------------------- phase 1 --
__global__ __launch_bounds__(32, 1)
void lif_phase1(const float* __restrict__ I)
{
    int w   = blockIdx.x;            // 0..511
    int lid = threadIdx.x;           // 0..31
    int neuron = w * 32 + lid;
    int b = neuron >> 9;
    int k = neuron & (K_ - 1);

    const float* ip = I + (int64_t)b * L_ * K_ + k;
    const float c2 = -0.5f - div_const_rn(-0.5f, 20.0f, 0.05f);

    float buf[NBUF][UNROLL];
#pragma unroll
    for (int p = 0; p < NBUF - 1; p++)
#pragma unroll
        for (int u = 0; u < UNROLL; u++)
            buf[p][u] = __ldcs(ip + (int64_t)(p * UNROLL + u) * K_);

    const float* ipn = ip + (int64_t)(NBUF - 1) * STRIDE;
    float uv = 0.0f, a = 0.0f, n = 0.0f;
    bool fire = false;

#pragma unroll 1
    for (int i = 0; i < NBATCH; i++) {
        int p = i & (NBUF - 1);
        const float* lp = (i + NBUF - 1 < NBATCH) ? ipn : ip;
#pragma unroll
        for (int u = 0; u < UNROLL; u++)
            buf[(p + NBUF - 1) & (NBUF - 1)][u] = __ldcs(lp + u * K_);
        ipn += STRIDE;

        if ((i & 31) == 0)                       // t = i*8 multiple of 256
            g_nckpt[i >> 5][neuron] = n;         // n BEFORE this chunk

        int t = i * UNROLL;
#pragma unroll
        for (int u = 0; u < UNROLL; u++) {
            float It = buf[p][u];
            float th = 1.0f + 1.5f * a;
            float uA = (uv - div_const_rn(uv, 20.0f, 0.05f)) + It;
            float uB = c2 + It;
            float un = fire ? uB : uA;
            bool f = (un >= th);
            float s = f ? 1.0f : 0.0f;
            unsigned m = __ballot_sync(0xFFFFFFFFu, f);
            if (lid == 0) __stcs(&g_masks[w][t + u], m);
            n = n + s;
            a = (a - div_const_rn(a, 100.0f, 0.01f)) + s;
            uv = un; fire = f;
        }
    }
}

// ---------------------------------------------------------------- phase 2 --
__global__ __launch_bounds__(256, 4)
void lif_phase2(float* __restrict__ spikes, float* __restrict__ series)
{
    int wg  = (blockIdx.x * blockDim.x + threadIdx.x) >> 5;  // 0..4095
    int lid = threadIdx.x & 31;
    int c = wg >> 9;               // chunk 0..7
    int w = wg & (NWARP - 1);      // neuron-warp 0..511

    int neuron = w * 32 + lid;
    int b = neuron >> 9;
    int k = neuron & (K_ - 1);
    int t0 = c * CHUNK;

    float n = g_nckpt[c][neuron];
    int64_t base = ((int64_t)b * L_ + t0) * K_ + k;
    float* sp = spikes + base;
    float* np = series + base;

#pragma unroll 1
    for (int g = 0; g < CHUNK / 32; g++) {       // 8 groups of 32 steps
        uint32_t mw = __ldcs(&g_masks[w][t0 + g * 32 + lid]);
#pragma unroll
        for (int u = 0; u < 32; u++) {
            uint32_t m = __shfl_sync(0xFFFFFFFFu, mw, u);
            float s = __uint_as_float(((m >> lid) & 1u) * 0x3F800000u);
            n = n + s;
            __stcs(sp + u * K_, s);
            __stcs(np + u * K_, n);
        }
        sp += 32 * K_; np += 32 * K_;
    }
}

extern "C" void kernel_launch(void* const* d_in, const int* in_sizes, int n_in,
                              void* d_out, int out_size)
{
    const float* I = (const float*)d_in[0];
    float* spikes = (float*)d_out;
    float* series = (float*)d_out + (int64_t)B_ * L_ * K_;

    lif_phase1<<<NWARP, 32>>>(I);                       // 512 blocks x 1 warp
    lif_phase2<<<(NWARP * NCHUNK) / 8, 256>>>(spikes, series); // 512 x 8 warps
}

// round 12
// speedup vs baseline: 1.0621x; 1.0621x over previous
#include <cuda_runtime.h>
#include <cstdint>

// MultiLIF: I[B=32, L=2048, K=512] -> (spikes[B,L,K], spike_series[B,L,K])
// d_out: spikes (B*L*K floats) then spike_series.
//
// R12 two-phase, both sides fixed vs R11 (phase1 was 210us due to per-step
// ballot/WARPSYNC/lane0-store):
//  Phase 1: R7 kernel (100us pedigree) with the 2 STG/step replaced by
//    register bit-packing -> 1 coalesced STG.32 per thread per 32 steps,
//    n checkpoint per 256 steps. No ballot, no divergence.
//  Phase 2: transposed mask layout [t/32][neuron] (no shfl); 4 neurons per
//    thread, float4 STG.128; 1024 warps; double-buffered mask loads.

static constexpr int B_ = 32;
static constexpr int L_ = 2048;
static constexpr int K_ = 512;
static constexpr int NEURONS = B_ * K_;          // 16384
static constexpr int UNROLL = 8;                 // phase-1 steps per batch
static constexpr int NBUF = 8;                   // phase-1 input ring depth
static constexpr int NBATCH = L_ / UNROLL;       // 256
static constexpr int STRIDE = UNROLL * K_;
static constexpr int CHUNK = 256;                // phase-2 steps per warp
static constexpr int NCHUNK = L_ / CHUNK;        // 8
static constexpr int NW32 = L_ / 32;             // 64 bit-windows

__device__ uint32_t g_bits[NW32][NEURONS];       // 4 MB  [t/32][neuron]
__device__ float    g_nckpt[NCHUNK][NEURONS];    // 512 KB [chunk][neuron]

__device__ __forceinline__ float div_const_rn(float x, float b, float y)
{
    // Markstein: correctly-rounded RN(x/b), y = RN(1/b). Branch-free;
    // == __fdiv_rn for all values reachable here.
    float q0 = __fmul_rn(x, y);
    float r  = __fmaf_rn(-b, q0, x);
    return __fmaf_rn(r, y, q0);
}

// ---------------------------------------------------------------- phase 1 --
__global__ __launch_bounds__(128, 1)
void lif_phase1(const float* __restrict__ I)
{
    int gid = blockIdx.x * blockDim.x + threadIdx.x;   // neuron 0..16383
    int b = gid >> 9;
    int k = gid & (K_ - 1);

    const float* ip = I + (int64_t)b * L_ * K_ + k;
    const float c2 = -0.5f - div_const_rn(-0.5f, 20.0f, 0.05f);

    float buf[NBUF][UNROLL];
#pragma unroll
    for (int p = 0; p < NBUF - 1; p++)
#pragma unroll
        for (int u = 0; u < UNROLL; u++)
            buf[p][u] = __ldcs(ip + (int64_t)(p * UNROLL + u) * K_);

    const float* ipn = ip + (int64_t)(NBUF - 1) * STRIDE;
    float uv = 0.0f, a = 0.0f, n = 0.0f;
    bool fire = false;
    uint32_t bits = 0;

#pragma unroll 1
    for (int i = 0; i < NBATCH; i++) {
        int p = i & (NBUF - 1);
        const float* lp = (i + NBUF - 1 < NBATCH) ? ipn : ip;
#pragma unroll
        for (int u = 0; u < UNROLL; u++)
            buf[(p + NBUF - 1) & (NBUF - 1)][u] = __ldcs(lp + u * K_);
        ipn += STRIDE;

        if ((i & 31) == 0)                         // every 256 steps
            __stcs(&g_nckpt[i >> 5][gid], n);      // n BEFORE this chunk

        int bpos = (i & 3) * UNROLL;               // bit base within window
#pragma unroll
        for (int u = 0; u < UNROLL; u++) {
            float It = buf[p][u];
            float th = 1.0f + 1.5f * a;
            float uA = (uv - div_const_rn(uv, 20.0f, 0.05f)) + It;
            float uB = c2 + It;
            float un = fire ? uB : uA;
            bool f = (un >= th);
            float s = f ? 1.0f : 0.0f;
            bits |= (f ? 1u : 0u) << (bpos + u);
            n = n + s;
            a = (a - div_const_rn(a, 100.0f, 0.01f)) + s;
            uv = un; fire = f;
        }
        if ((i & 3) == 3) {                        // window of 32 steps done
            __stcs(&g_bits[i >> 2][gid], bits);    // coalesced across lanes
            bits = 0;
        }
    }
}

// ---------------------------------------------------------------- phase 2 --
__global__ __launch_bounds__(128, 8)
void lif_phase2(float* __restrict__ spikes, float* __restrict__ series)
{
    int bx = blockIdx.x;                 // 256 blocks
    int c = bx >> 5;                     // chunk 0..7
    int local = (bx & 31) * 128 + threadIdx.x;   // 0..4095
    int nbase = local * 4;               // first of 4 owned neurons
    int b = nbase >> 9;
    int k = nbase & (K_ - 1);
    int t0 = c * CHUNK;

    float4 n4 = *(const float4*)&g_nckpt[c][nbase];

    int64_t base = ((int64_t)b * L_ + t0) * K_ + k;
    float4* sp = (float4*)(spikes + base);
    float4* np = (float4*)(series + base);
    const int s4 = K_ / 4;               // float4 stride per timestep

    uint4 cur = *(const uint4*)&g_bits[t0 >> 5][nbase];

#pragma unroll 1
    for (int w = 0; w < CHUNK / 32; w++) {        // 8 windows of 32 steps
        uint4 nxt = (w + 1 < CHUNK / 32)
                    ? *(const uint4*)&g_bits[(t0 >> 5) + w + 1][nbase]
                    : cur;
#pragma unroll
        for (int u = 0; u < 32; u++) {
            float4 s;
            s.x = ((cur.x >> u) & 1u) ? 1.0f : 0.0f;
            s.y = ((cur.y >> u) & 1u) ? 1.0f : 0.0f;
            s.z = ((cur.z >> u) & 1u) ? 1.0f : 0.0f;
            s.w = ((cur.w >> u) & 1u) ? 1.0f : 0.0f;
            n4.x += s.x; n4.y += s.y; n4.z += s.z; n4.w += s.w;
            __stcs(sp + u * s4, s);
            __stcs(np + u * s4, n4);
        }
        sp += 32 * s4; np += 32 * s4;
        cur = nxt;
    }
}

extern "C" void kernel_launch(void* const* d_in, const int* in_sizes, int n_in,
                              void* d_out, int out_size)
{
    const float* I = (const float*)d_in[0];
    float* spikes = (float*)d_out;
    float* series = (float*)d_out + (int64_t)B_ * L_ * K_;

    lif_phase1<<<NEURONS / 128, 128>>>(I);            // 128 blocks x 128 thr
    lif_phase2<<<NCHUNK * 32, 128>>>(spikes, series); // 256 blocks x 128 thr
}

// round 13
// speedup vs baseline: 2.3396x; 2.2028x over previous
#include <cuda_runtime.h>
#include <cstdint>

// MultiLIF: I[B=32, L=2048, K=512] -> (spikes[B,L,K], spike_series[B,L,K])
// d_out: spikes (B*L*K floats) then spike_series.
//
// R13: two-phase, phase1 de-spilled. R11/R12 phase1 (~205us) indexed the
// input ring with a RUNTIME p -> buf[][] demoted to local memory (LDL/STL
// every element). Restored R7's structure: outer g-loop, fully-unrolled
// inner p-loop, ALL ring indices compile-time. Bit-pack spike export
// (1 STG.32 / 32 steps), n via exact __popc per window, checkpoint per 64
// steps. Phase2: chunk 64 -> 1024 blocks (28 warps/SM) to saturate DRAM.

static constexpr int B_ = 32;
static constexpr int L_ = 2048;
static constexpr int K_ = 512;
static constexpr int NEURONS = B_ * K_;          // 16384
static constexpr int UNROLL = 8;                 // phase-1 steps per batch
static constexpr int NBUF = 8;                   // phase-1 ring depth
static constexpr int NBATCH = L_ / UNROLL;       // 256
static constexpr int GROUPS = NBATCH / NBUF;     // 32
static constexpr int STRIDE = UNROLL * K_;
static constexpr int CHUNK = 64;                 // phase-2 steps per thread
static constexpr int NCHUNK = L_ / CHUNK;        // 32 (== GROUPS)
static constexpr int NW32 = L_ / 32;             // 64 bit-windows

__device__ uint32_t g_bits[NW32][NEURONS];       // 4 MB   [t/32][neuron]
__device__ float    g_nckpt[NCHUNK][NEURONS];    // 2 MB   [chunk][neuron]

__device__ __forceinline__ float div_const_rn(float x, float b, float y)
{
    // Markstein: correctly-rounded RN(x/b), y = RN(1/b). Branch-free;
    // == __fdiv_rn for all values reachable here.
    float q0 = __fmul_rn(x, y);
    float r  = __fmaf_rn(-b, q0, x);
    return __fmaf_rn(r, y, q0);
}

// ---------------------------------------------------------------- phase 1 --
__global__ __launch_bounds__(128, 1)
void lif_phase1(const float* __restrict__ I)
{
    int gid = blockIdx.x * blockDim.x + threadIdx.x;   // neuron 0..16383
    int b = gid >> 9;
    int k = gid & (K_ - 1);

    const float* ip = I + (int64_t)b * L_ * K_ + k;
    const float c2 = -0.5f - div_const_rn(-0.5f, 20.0f, 0.05f);

    float buf[NBUF][UNROLL];
#pragma unroll
    for (int p = 0; p < NBUF - 1; p++)
#pragma unroll
        for (int u = 0; u < UNROLL; u++)
            buf[p][u] = __ldcs(ip + (int64_t)(p * UNROLL + u) * K_);

    const float* ipn = ip + (int64_t)(NBUF - 1) * STRIDE;
    float uv = 0.0f, a = 0.0f, n = 0.0f;
    bool fire = false;
    uint32_t bits = 0;

#pragma unroll 1
    for (int g = 0; g < GROUPS; g++) {
        // n BEFORE this 64-step chunk (chunk index == g)
        __stcs(&g_nckpt[g][gid], n);
#pragma unroll
        for (int p = 0; p < NBUF; p++) {           // p COMPILE-TIME
            int loadidx = g * NBUF + p + (NBUF - 1);
            const float* lp = (loadidx < NBATCH) ? ipn : ip;
#pragma unroll
            for (int u = 0; u < UNROLL; u++)
                buf[(p + NBUF - 1) & (NBUF - 1)][u] = __ldcs(lp + u * K_);
            ipn += STRIDE;

#pragma unroll
            for (int u = 0; u < UNROLL; u++) {
                float It = buf[p][u];
                float th = 1.0f + 1.5f * a;
                float uA = (uv - div_const_rn(uv, 20.0f, 0.05f)) + It;
                float uB = c2 + It;
                float un = fire ? uB : uA;
                bool f = (un >= th);
                float s = f ? 1.0f : 0.0f;
                bits |= (f ? 1u : 0u) << (((p & 3) * UNROLL) + u); // const pos
                a = (a - div_const_rn(a, 100.0f, 0.01f)) + s;
                uv = un; fire = f;
            }
            if ((p & 3) == 3) {                    // 32-step window complete
                __stcs(&g_bits[g * 2 + (p >> 2)][gid], bits);
                n = n + (float)__popc(bits);       // exact integer float adds
                bits = 0;
            }
        }
    }
}

// ---------------------------------------------------------------- phase 2 --
__global__ __launch_bounds__(128, 8)
void lif_phase2(float* __restrict__ spikes, float* __restrict__ series)
{
    int bx = blockIdx.x;                         // 1024 blocks
    int c = bx >> 5;                             // chunk 0..31
    int local = (bx & 31) * 128 + threadIdx.x;   // 0..4095
    int nbase = local * 4;                       // first of 4 owned neurons
    int b = nbase >> 9;
    int k = nbase & (K_ - 1);
    int t0 = c * CHUNK;

    float4 n4 = *(const float4*)&g_nckpt[c][nbase];

    int64_t base = ((int64_t)b * L_ + t0) * K_ + k;
    float4* sp = (float4*)(spikes + base);
    float4* np = (float4*)(series + base);
    const int s4 = K_ / 4;                       // float4 stride per timestep

    uint4 w0 = *(const uint4*)&g_bits[t0 >> 5][nbase];
    uint4 w1 = *(const uint4*)&g_bits[(t0 >> 5) + 1][nbase];

#pragma unroll 1
    for (int w = 0; w < CHUNK / 32; w++) {       // 2 windows of 32 steps
        uint4 cur = (w == 0) ? w0 : w1;
#pragma unroll
        for (int u = 0; u < 32; u++) {
            float4 s;
            s.x = ((cur.x >> u) & 1u) ? 1.0f : 0.0f;
            s.y = ((cur.y >> u) & 1u) ? 1.0f : 0.0f;
            s.z = ((cur.z >> u) & 1u) ? 1.0f : 0.0f;
            s.w = ((cur.w >> u) & 1u) ? 1.0f : 0.0f;
            n4.x += s.x; n4.y += s.y; n4.z += s.z; n4.w += s.w;
            __stcs(sp + u * s4, s);
            __stcs(np + u * s4, n4);
        }
        sp += 32 * s4; np += 32 * s4;
    }
}

extern "C" void kernel_launch(void* const* d_in, const int* in_sizes, int n_in,
                              void* d_out, int out_size)
{
    const float* I = (const float*)d_in[0];
    float* spikes = (float*)d_out;
    float* series = (float*)d_out + (int64_t)B_ * L_ * K_;

    lif_phase1<<<NEURONS / 128, 128>>>(I);             // 128 x 128
    lif_phase2<<<NCHUNK * 32, 128>>>(spikes, series);  // 1024 x 128
}